// round 11
// baseline (speedup 1.0000x reference)
#include <cuda_runtime.h>

#define LSEQ 256
#define CIN  8
#define COUT 8
#define HID  32
#define XPAD 12     // conv arrays: padded row stride (floats), conflict-free LDS.128
#define H1PAD 36    // sh1 row stride (floats)
#define W2PAD 36    // sW2 row stride (floats): rows land on distinct banks
#define NBLK 128
#define NTHR 1024
#define GRP  16     // blocks per o-group

// Scratch: K[o][d][c]
__device__ __align__(16) float g_K[COUT * LSEQ * CIN];
// Per-group barrier state (self-resetting for graph replay)
__device__ volatile unsigned g_bar[COUT] = {0};
__device__ unsigned          g_dep[COUT] = {0};

// ---------------------------------------------------------------------------
// Fused kernel: 128 blocks x 1024 threads, one CTA/SM.
// Phase 1a: cooperative h1 (one sin per value) -> smem.
// Phase 1b: 8 threads/point; lane q evaluates neurons k = q + 8m; W2PAD=36
//           makes every W2/h1 LDS.128 conflict-free (verified R10).
// Group barrier: 8 groups of 16 blocks; fence/atomic by ONE thread per block
//           (CG grid-sync pattern) instead of 1024 MEMBAR.GPUs.
// Phase 2: causal conv; 32 warps = 16 positions x 2 d-halves, smem combine.
// ---------------------------------------------------------------------------
__global__ __launch_bounds__(NTHR, 1) void ckconv_fused(
    const float* __restrict__ x,
    const float* __restrict__ v1, const float* __restrict__ g1,
    const float* __restrict__ b1,
    const float* __restrict__ v2, const float* __restrict__ g2,
    const float* __restrict__ b2,
    const float* __restrict__ w3, const float* __restrict__ b3,
    float* __restrict__ out)
{
    __shared__ float  sW1[HID][3];
    __shared__ float  sb1[HID];
    __shared__ __align__(16) float sW2[HID * W2PAD];   // normalized, padded rows
    __shared__ float  sb2[HID];
    __shared__ float  sw3[HID];
    __shared__ float  sb3;
    __shared__ float  spart[32];                        // conv half-sums
    __shared__ __align__(16) float sh1[128 * H1PAD];    // h1[point][h]
    __shared__ __align__(16) float sk[LSEQ * XPAD];
    __shared__ __align__(16) float sx[LSEQ * XPAD];

    int tid = threadIdx.x;

    // ---------------- phase 0: stage x + weight prep ------------------------
    if (tid < 512) {
        int r = tid >> 1, hh = (tid & 1) << 2;
        *(float4*)&sx[r * XPAD + hh] = ((const float4*)x)[tid];
    }
    if (tid >= 512 && tid < 768) {
        int e = tid - 512;                       // one float4 of v2 per thread
        float4 w4 = ((const float4*)v2)[e];
        float ss = w4.x * w4.x + w4.y * w4.y + w4.z * w4.z + w4.w * w4.w;
        ss += __shfl_xor_sync(0xFFFFFFFFu, ss, 1);
        ss += __shfl_xor_sync(0xFFFFFFFFu, ss, 2);
        ss += __shfl_xor_sync(0xFFFFFFFFu, ss, 4);
        int row = e >> 3;
        float inv = g2[row] * rsqrtf(ss);
        float4 nw;
        nw.x = w4.x * inv; nw.y = w4.y * inv; nw.z = w4.z * inv; nw.w = w4.w * inv;
        *(float4*)&sW2[row * W2PAD + ((e & 7) << 2)] = nw;
    }
    if (tid >= 768 && tid < 768 + HID) {
        int h = tid - 768;
        float a = v1[h * 3 + 0];
        float b = v1[h * 3 + 1];
        float c = v1[h * 3 + 2];
        float inv1 = g1[h] * rsqrtf(a * a + b * b + c * c);
        sW1[h][0] = a * inv1;
        sW1[h][1] = b * inv1;
        sW1[h][2] = c * inv1;
        sb1[h] = b1[h];
        sb2[h] = b2[h];
        sw3[h] = w3[h];
        if (h == 0) sb3 = b3[0];
    }
    __syncthreads();

    // ---------------- point coordinates (8 threads share point p) -----------
    int p   = tid >> 3;                          // local point 0..127
    int q   = tid & 7;
    int pid = blockIdx.x * 128 + p;              // global point
    int c = pid & 7;
    int d = (pid >> 3) & 255;
    int o = pid >> 11;

    float dt = -(float)d * (1.0f / 256.0f);
    float fc = (float)c;
    float fo = (float)o;

    // ---------------- phase 1a: h1 (4 values per thread) --------------------
    {
        float4 hv;
        float* hvp = (float*)&hv;
        #pragma unroll
        for (int m = 0; m < 4; m++) {
            int h = (q << 2) + m;
            float z = fmaf(dt, sW1[h][0], fmaf(fc, sW1[h][1], fmaf(fo, sW1[h][2], sb1[h])));
            hvp[m] = __sinf(z);                  // OMEGA = 1
        }
        *(float4*)&sh1[p * H1PAD + (q << 2)] = hv;
    }
    __syncthreads();

    // ---------------- phase 1b: neurons k = q + 8m ---------------------------
    float acc;
    {
        const float* h1row = &sh1[p * H1PAD];
        const float* r0 = &sW2[(q     ) * W2PAD];
        const float* r1 = &sW2[(q +  8) * W2PAD];
        const float* r2 = &sW2[(q + 16) * W2PAD];
        const float* r3 = &sW2[(q + 24) * W2PAD];

        float z0 = sb2[q], z1 = sb2[q + 8], z2 = sb2[q + 16], z3 = sb2[q + 24];

        #pragma unroll
        for (int j = 0; j < 8; j++) {
            float4 h  = *(const float4*)&h1row[4 * j];
            float4 w0 = *(const float4*)&r0[4 * j];
            float4 w1 = *(const float4*)&r1[4 * j];
            float4 w2 = *(const float4*)&r2[4 * j];
            float4 w3v = *(const float4*)&r3[4 * j];
            z0 = fmaf(h.x, w0.x, z0); z0 = fmaf(h.y, w0.y, z0);
            z0 = fmaf(h.z, w0.z, z0); z0 = fmaf(h.w, w0.w, z0);
            z1 = fmaf(h.x, w1.x, z1); z1 = fmaf(h.y, w1.y, z1);
            z1 = fmaf(h.z, w1.z, z1); z1 = fmaf(h.w, w1.w, z1);
            z2 = fmaf(h.x, w2.x, z2); z2 = fmaf(h.y, w2.y, z2);
            z2 = fmaf(h.z, w2.z, z2); z2 = fmaf(h.w, w2.w, z2);
            z3 = fmaf(h.x, w3v.x, z3); z3 = fmaf(h.y, w3v.y, z3);
            z3 = fmaf(h.z, w3v.z, z3); z3 = fmaf(h.w, w3v.w, z3);
        }

        acc =       __sinf(z0) * sw3[q];
        acc = fmaf(__sinf(z1), sw3[q + 8],  acc);
        acc = fmaf(__sinf(z2), sw3[q + 16], acc);
        acc = fmaf(__sinf(z3), sw3[q + 24], acc);

        acc += __shfl_xor_sync(0xFFFFFFFFu, acc, 1);
        acc += __shfl_xor_sync(0xFFFFFFFFu, acc, 2);
        acc += __shfl_xor_sync(0xFFFFFFFFu, acc, 4);
    }
    if (q == 0)
        g_K[pid] = acc + sb3;

    // ---------------- group barrier (16 blocks sharing o) -------------------
    // CG grid-sync pattern: fence + atomic by ONE thread, not 1024 MEMBARs.
    int grp = blockIdx.x >> 4;
    __syncthreads();                  // all block's g_K stores happen-before tid0
    if (tid == 0) {
        __threadfence();              // release g_K to GPU scope
        atomicAdd((unsigned*)&g_bar[grp], 1u);
        while (g_bar[grp] < GRP) { }
        __threadfence();              // acquire peers' g_K
    }
    __syncthreads();

    // ---------------- phase 2: causal conv ----------------------------------
    int oc   = grp;
    int base = (blockIdx.x & 15) << 4;           // 16 positions per block

    const float4* k4 = (const float4*)(g_K + oc * (LSEQ * CIN));
    if (tid < 512) {
        int r = tid >> 1, hh = (tid & 1) << 2;
        float4 kv = __ldcg(k4 + tid);            // L2-coherent (peer-written)
        *(float4*)&sk[r * XPAD + hh] = kv;
    }
    __syncthreads();

    {
        int w = tid >> 5, l = tid & 31;
        int i    = base + (w & 15);              // warp pair shares position i
        int half = w >> 4;                       // 0: d<128, 1: d>=128

        float acc2 = 0.f;
        #pragma unroll
        for (int it4 = 0; it4 < 4; it4++) {
            int it = (half << 2) + it4;
            if ((it << 5) > i) break;            // warp-uniform early exit
            int dd = l + (it << 5);
            float4 ka = *(const float4*)&sk[dd * XPAD];
            float4 kb = *(const float4*)&sk[dd * XPAD + 4];

            bool v = dd <= i;
            int jc = v ? (i - dd) : 0;
            float m = v ? 1.f : 0.f;

            float4 a0 = *(const float4*)&sx[jc * XPAD];
            float4 b0 = *(const float4*)&sx[jc * XPAD + 4];

            float t = ka.x * a0.x;
            t = fmaf(ka.y, a0.y, t);
            t = fmaf(ka.z, a0.z, t);
            t = fmaf(ka.w, a0.w, t);
            t = fmaf(kb.x, b0.x, t);
            t = fmaf(kb.y, b0.y, t);
            t = fmaf(kb.z, b0.z, t);
            t = fmaf(kb.w, b0.w, t);
            acc2 = fmaf(m, t, acc2);
        }

        #pragma unroll
        for (int s = 16; s > 0; s >>= 1)
            acc2 += __shfl_xor_sync(0xFFFFFFFFu, acc2, s);

        if (l == 0)
            spart[w] = acc2;
    }
    __syncthreads();

    if (tid < 16)
        out[(base + tid) * COUT + oc] = spart[tid] + spart[tid + 16];

    // ---------------- barrier reset (depart counter, replay-safe) -----------
    __syncthreads();
    if (tid == 0) {
        if (atomicAdd(&g_dep[grp], 1u) == GRP - 1u) {
            g_dep[grp] = 0u;
            *(unsigned*)&g_bar[grp] = 0u;
        }
    }
}

// ---------------------------------------------------------------------------
// Launch. Input order: x, t, v1, g1, b1, v2, g2, b2, w3, b3.
// t is the uniform grid arange(L)/L; folded analytically into dt = -d/L.
// ---------------------------------------------------------------------------
extern "C" void kernel_launch(void* const* d_in, const int* in_sizes, int n_in,
                              void* d_out, int out_size)
{
    const float* x  = (const float*)d_in[0];
    const float* v1 = (const float*)d_in[2];
    const float* g1 = (const float*)d_in[3];
    const float* b1 = (const float*)d_in[4];
    const float* v2 = (const float*)d_in[5];
    const float* g2 = (const float*)d_in[6];
    const float* b2 = (const float*)d_in[7];
    const float* w3 = (const float*)d_in[8];
    const float* b3 = (const float*)d_in[9];
    float* out = (float*)d_out;

    ckconv_fused<<<NBLK, NTHR>>>(x, v1, g1, b1, v2, g2, b2, w3, b3, out);
}

// round 12
// speedup vs baseline: 1.2186x; 1.2186x over previous
#include <cuda_runtime.h>

#define LSEQ 256
#define CIN  8
#define COUT 8
#define HID  32
#define XPAD 12     // conv arrays: padded row stride (floats)
#define H1PAD 36    // sh1 row stride
#define W2PAD 36    // sW2 row stride: conflict-free broadcast loads
#define NBLK 128
#define NTHR 256
#define GRP  16     // blocks per o-group

// Scratch: K[o][d][c]
__device__ __align__(16) float g_K[COUT * LSEQ * CIN];
// Per-group barrier state (self-resetting for graph replay)
__device__ volatile unsigned g_bar[COUT] = {0};
__device__ unsigned          g_dep[COUT] = {0};

// ---------------------------------------------------------------------------
// Fused kernel: 128 blocks x 256 threads (single wave).
// Phase 1a: thread (pp,q) computes h1[p][4q..4q+3] for 4 points p=pp+32i.
// Phase 1b: same thread evaluates neurons k=q+8m for its 4 points:
//           per j, 4 h-loads + 4 W2-loads feed 64 FMAs -> LDS wavefronts
//           per SM drop 5120 -> 2048, balancing the FMA pipe.
// Group barrier: 16 blocks per out-channel, one-thread fence.
// Phase 2: causal conv from smem, 8 warps x 2 positions.
// ---------------------------------------------------------------------------
__global__ __launch_bounds__(NTHR, 1) void ckconv_fused(
    const float* __restrict__ x,
    const float* __restrict__ v1, const float* __restrict__ g1,
    const float* __restrict__ b1,
    const float* __restrict__ v2, const float* __restrict__ g2,
    const float* __restrict__ b2,
    const float* __restrict__ w3, const float* __restrict__ b3,
    float* __restrict__ out)
{
    __shared__ float  sW1[HID][3];
    __shared__ float  sb1[HID];
    __shared__ __align__(16) float sW2[HID * W2PAD];
    __shared__ float  sb2[HID];
    __shared__ float  sw3[HID];
    __shared__ float  sb3;
    __shared__ __align__(16) float sh1[128 * H1PAD];
    __shared__ __align__(16) float sk[LSEQ * XPAD];
    __shared__ __align__(16) float sx[LSEQ * XPAD];

    int tid = threadIdx.x;

    // ---------------- phase 0: stage x + weight prep ------------------------
    {
        int r = tid >> 1, hh = (tid & 1) << 2;
        *(float4*)&sx[r * XPAD + hh]         = ((const float4*)x)[tid];
        *(float4*)&sx[(r + 128) * XPAD + hh] = ((const float4*)x)[tid + 256];
    }
    {
        float4 w4 = ((const float4*)v2)[tid];          // 256 float4 = all of v2
        float ss = w4.x * w4.x + w4.y * w4.y + w4.z * w4.z + w4.w * w4.w;
        ss += __shfl_xor_sync(0xFFFFFFFFu, ss, 1);
        ss += __shfl_xor_sync(0xFFFFFFFFu, ss, 2);
        ss += __shfl_xor_sync(0xFFFFFFFFu, ss, 4);
        int row = tid >> 3;
        float inv = g2[row] * rsqrtf(ss);
        float4 nw;
        nw.x = w4.x * inv; nw.y = w4.y * inv; nw.z = w4.z * inv; nw.w = w4.w * inv;
        *(float4*)&sW2[row * W2PAD + ((tid & 7) << 2)] = nw;
    }
    if (tid < HID) {
        float a = v1[tid * 3 + 0];
        float b = v1[tid * 3 + 1];
        float c = v1[tid * 3 + 2];
        float inv1 = g1[tid] * rsqrtf(a * a + b * b + c * c);
        sW1[tid][0] = a * inv1;
        sW1[tid][1] = b * inv1;
        sW1[tid][2] = c * inv1;
        sb1[tid] = b1[tid];
        sb2[tid] = b2[tid];
        sw3[tid] = w3[tid];
        if (tid == 0) sb3 = b3[0];
    }
    __syncthreads();

    // ---------------- coordinates -------------------------------------------
    int pp = tid >> 3;                         // 0..31: point-group
    int q  = tid & 7;
    int oc    = blockIdx.x >> 4;               // out channel (block-uniform)
    int dbase = (blockIdx.x & 15) << 4;        // d-tile / conv i-tile base
    float fc = (float)(pp & 7);
    float fo = (float)oc;
    int d0 = dbase + (pp >> 3);                // point i: d = d0 + 4i

    // ---------------- phase 1a: h1[p][4q..4q+3] for 4 points ----------------
    {
        float4 hv[4];
        #pragma unroll
        for (int m = 0; m < 4; m++) {
            int h = (q << 2) + m;
            float zb = fmaf(fc, sW1[h][1], fmaf(fo, sW1[h][2], sb1[h]));
            float w0 = sW1[h][0];
            #pragma unroll
            for (int i = 0; i < 4; i++) {
                float dt = -(float)(d0 + (i << 2)) * (1.0f / 256.0f);
                ((float*)&hv[i])[m] = __sinf(fmaf(dt, w0, zb));  // OMEGA = 1
            }
        }
        #pragma unroll
        for (int i = 0; i < 4; i++)
            *(float4*)&sh1[(pp + (i << 5)) * H1PAD + (q << 2)] = hv[i];
    }
    __syncthreads();

    // ---------------- phase 1b: neurons k=q+8m, 4 points ---------------------
    {
        const float* r0 = &sW2[(q     ) * W2PAD];
        const float* r1 = &sW2[(q +  8) * W2PAD];
        const float* r2 = &sW2[(q + 16) * W2PAD];
        const float* r3 = &sW2[(q + 24) * W2PAD];

        float z0[4], z1[4], z2[4], z3[4];
        #pragma unroll
        for (int i = 0; i < 4; i++) {
            z0[i] = sb2[q];
            z1[i] = sb2[q + 8];
            z2[i] = sb2[q + 16];
            z3[i] = sb2[q + 24];
        }

        #pragma unroll
        for (int j = 0; j < 8; j++) {
            float4 h[4];
            #pragma unroll
            for (int i = 0; i < 4; i++)
                h[i] = *(const float4*)&sh1[(pp + (i << 5)) * H1PAD + 4 * j];

            float4 w;
            w = *(const float4*)&r0[4 * j];
            #pragma unroll
            for (int i = 0; i < 4; i++) {
                z0[i] = fmaf(h[i].x, w.x, z0[i]); z0[i] = fmaf(h[i].y, w.y, z0[i]);
                z0[i] = fmaf(h[i].z, w.z, z0[i]); z0[i] = fmaf(h[i].w, w.w, z0[i]);
            }
            w = *(const float4*)&r1[4 * j];
            #pragma unroll
            for (int i = 0; i < 4; i++) {
                z1[i] = fmaf(h[i].x, w.x, z1[i]); z1[i] = fmaf(h[i].y, w.y, z1[i]);
                z1[i] = fmaf(h[i].z, w.z, z1[i]); z1[i] = fmaf(h[i].w, w.w, z1[i]);
            }
            w = *(const float4*)&r2[4 * j];
            #pragma unroll
            for (int i = 0; i < 4; i++) {
                z2[i] = fmaf(h[i].x, w.x, z2[i]); z2[i] = fmaf(h[i].y, w.y, z2[i]);
                z2[i] = fmaf(h[i].z, w.z, z2[i]); z2[i] = fmaf(h[i].w, w.w, z2[i]);
            }
            w = *(const float4*)&r3[4 * j];
            #pragma unroll
            for (int i = 0; i < 4; i++) {
                z3[i] = fmaf(h[i].x, w.x, z3[i]); z3[i] = fmaf(h[i].y, w.y, z3[i]);
                z3[i] = fmaf(h[i].z, w.z, z3[i]); z3[i] = fmaf(h[i].w, w.w, z3[i]);
            }
        }

        float s0 = sw3[q], s1 = sw3[q + 8], s2 = sw3[q + 16], s3 = sw3[q + 24];
        #pragma unroll
        for (int i = 0; i < 4; i++) {
            float acc =        __sinf(z0[i]) * s0;
            acc = fmaf(__sinf(z1[i]), s1, acc);
            acc = fmaf(__sinf(z2[i]), s2, acc);
            acc = fmaf(__sinf(z3[i]), s3, acc);
            acc += __shfl_xor_sync(0xFFFFFFFFu, acc, 1);
            acc += __shfl_xor_sync(0xFFFFFFFFu, acc, 2);
            acc += __shfl_xor_sync(0xFFFFFFFFu, acc, 4);
            if (q == 0)
                g_K[blockIdx.x * 128 + pp + (i << 5)] = acc + sb3;
        }
    }

    // ---------------- group barrier (16 blocks sharing o) -------------------
    int grp = oc;
    __syncthreads();
    if (tid == 0) {
        __threadfence();
        atomicAdd((unsigned*)&g_bar[grp], 1u);
        while (g_bar[grp] < GRP) { }
        __threadfence();
    }
    __syncthreads();

    // ---------------- phase 2: causal conv ----------------------------------
    const float4* k4 = (const float4*)(g_K + oc * (LSEQ * CIN));
    {
        int r = tid >> 1, hh = (tid & 1) << 2;
        float4 a = __ldcg(k4 + tid);
        float4 b = __ldcg(k4 + tid + 256);
        *(float4*)&sk[r * XPAD + hh]         = a;
        *(float4*)&sk[(r + 128) * XPAD + hh] = b;
    }
    __syncthreads();

    {
        int w = tid >> 5, l = tid & 31;        // 8 warps -> 2 positions each
        int i1 = dbase + 2 * w + 1;
        int i0 = i1 - 1;

        float acc0 = 0.f, acc1 = 0.f;
        #pragma unroll
        for (int it = 0; it < 8; it++) {
            if ((it << 5) > i1) break;         // warp-uniform early exit
            int dd = l + (it << 5);
            float4 ka = *(const float4*)&sk[dd * XPAD];
            float4 kb = *(const float4*)&sk[dd * XPAD + 4];

            int j1 = i1 - dd;
            bool v0 = dd <= i0, v1 = dd <= i1;
            int jc0 = v0 ? (j1 - 1) : 0;
            int jc1 = v1 ? j1 : 0;
            float m0 = v0 ? 1.f : 0.f;
            float m1 = v1 ? 1.f : 0.f;

            float4 a0 = *(const float4*)&sx[jc0 * XPAD];
            float4 b0 = *(const float4*)&sx[jc0 * XPAD + 4];
            float4 a1 = *(const float4*)&sx[jc1 * XPAD];
            float4 b1 = *(const float4*)&sx[jc1 * XPAD + 4];

            float t0 = ka.x * a0.x;
            t0 = fmaf(ka.y, a0.y, t0);
            t0 = fmaf(ka.z, a0.z, t0);
            t0 = fmaf(ka.w, a0.w, t0);
            t0 = fmaf(kb.x, b0.x, t0);
            t0 = fmaf(kb.y, b0.y, t0);
            t0 = fmaf(kb.z, b0.z, t0);
            t0 = fmaf(kb.w, b0.w, t0);
            acc0 = fmaf(m0, t0, acc0);

            float t1 = ka.x * a1.x;
            t1 = fmaf(ka.y, a1.y, t1);
            t1 = fmaf(ka.z, a1.z, t1);
            t1 = fmaf(ka.w, a1.w, t1);
            t1 = fmaf(kb.x, b1.x, t1);
            t1 = fmaf(kb.y, b1.y, t1);
            t1 = fmaf(kb.z, b1.z, t1);
            t1 = fmaf(kb.w, b1.w, t1);
            acc1 = fmaf(m1, t1, acc1);
        }

        #pragma unroll
        for (int s = 16; s > 0; s >>= 1) {
            acc0 += __shfl_xor_sync(0xFFFFFFFFu, acc0, s);
            acc1 += __shfl_xor_sync(0xFFFFFFFFu, acc1, s);
        }

        if (l == 0) {
            out[i0 * COUT + oc] = acc0;
            out[i1 * COUT + oc] = acc1;
        }
    }

    // ---------------- barrier reset (depart counter, replay-safe) -----------
    __syncthreads();
    if (tid == 0) {
        if (atomicAdd(&g_dep[grp], 1u) == GRP - 1u) {
            g_dep[grp] = 0u;
            *(unsigned*)&g_bar[grp] = 0u;
        }
    }
}

// ---------------------------------------------------------------------------
// Launch. Input order: x, t, v1, g1, b1, v2, g2, b2, w3, b3.
// t is the uniform grid arange(L)/L; folded analytically into dt = -d/L.
// ---------------------------------------------------------------------------
extern "C" void kernel_launch(void* const* d_in, const int* in_sizes, int n_in,
                              void* d_out, int out_size)
{
    const float* x  = (const float*)d_in[0];
    const float* v1 = (const float*)d_in[2];
    const float* g1 = (const float*)d_in[3];
    const float* b1 = (const float*)d_in[4];
    const float* v2 = (const float*)d_in[5];
    const float* g2 = (const float*)d_in[6];
    const float* b2 = (const float*)d_in[7];
    const float* w3 = (const float*)d_in[8];
    const float* b3 = (const float*)d_in[9];
    float* out = (float*)d_out;

    ckconv_fused<<<NBLK, NTHR>>>(x, v1, g1, b1, v2, g2, b2, w3, b3, out);
}